// round 16
// baseline (speedup 1.0000x reference)
#include <cuda_runtime.h>
#include <cuda_pipeline.h>
#include <math.h>
#include <stdint.h>

#define B_    8
#define L_    2048
#define DIM_  4096
#define DV_   1024
#define H_    16
#define DH_   64
#define NS_   32
#define M_    (B_*L_)
#define N2_   (2*DV_)
#define AVS   64                     /* attention split slots (2 per block) */

// ---------------- scratch (static device memory, alloc-free) ----------------
__device__ float    g_K [M_*DV_];
__device__ float    g_V [M_*DV_];
__device__ uint32_t g_Xt[M_*DIM_];
__device__ uint32_t g_Wt[N2_*DIM_];
__device__ float    g_Qp[NS_*DV_];
__device__ float    g_AOp[AVS*B_*NS_*DV_];  // 64 MB partial O (unnormalized)
__device__ float    g_M  [AVS*B_*H_*NS_];
__device__ float    g_S  [AVS*B_*H_*NS_];
__device__ float    g_X  [B_*NS_*DV_];      // LN0 output
__device__ float    g_O2 [B_*NS_*DV_];

__device__ __forceinline__ uint32_t f2tf32(float x) {
    uint32_t u;
    asm("cvt.rna.tf32.f32 %0, %1;" : "=r"(u) : "f"(x));
    return u;
}

__device__ __forceinline__ float warp_red_sum(float v){
    #pragma unroll
    for (int o=16;o;o>>=1) v += __shfl_xor_sync(0xffffffffu, v, o);
    return v;
}

// -------- prepass: fp32 -> tf32, fragment-major tile layouts (fused) ----------
#define XT_BLOCKS (M_*DIM_/(256*4))
#define WT_BLOCKS (N2_*DIM_/(256*4))

__global__ __launch_bounds__(256) void cvt_kernel(
    const float* __restrict__ X,
    const float* __restrict__ Wk, const float* __restrict__ Wv)
{
    if (blockIdx.x < XT_BLOCKS) {
        uint32_t g = blockIdx.x*256 + threadIdx.x;
        uint32_t tile = g >> 5, lane = g & 31;
        uint32_t rt = tile >> 9, kt8 = tile & 511;
        uint32_t lr = lane >> 2, lc = lane & 3;
        const float* p = X + (size_t)(rt*16 + lr)*DIM_ + kt8*8 + lc;
        uint4 o;
        o.x = f2tf32(p[0]);
        o.y = f2tf32(p[8*DIM_]);
        o.z = f2tf32(p[4]);
        o.w = f2tf32(p[8*DIM_ + 4]);
        *(uint4*)(g_Xt + (size_t)g*4) = o;
    } else {
        uint32_t g = (blockIdx.x - XT_BLOCKS)*256 + threadIdx.x;
        uint32_t tile = g >> 5, lane = g & 31;
        uint32_t nt = tile >> 8, kt16 = tile & 255;
        uint32_t lr = lane >> 2, lc = lane & 3;
        uint32_t n = nt*8 + lr;
        const float* src = (n < DV_) ? (Wk + (size_t)n*DIM_) : (Wv + (size_t)(n - DV_)*DIM_);
        const float* p = src + kt16*16 + lc;
        uint4 o;
        o.x = f2tf32(p[0]);
        o.y = f2tf32(p[4]);
        o.z = f2tf32(p[8]);
        o.w = f2tf32(p[12]);
        *(uint4*)(g_Wt + (size_t)g*4) = o;
    }
}

// ============ fused K/V projection GEMM: mma.sync m16n8k8 TF32 ==============
#define BM    128
#define BN    128
#define BK    32
#define NSTG  3
#define STG_U 8192

__device__ __forceinline__ void mma_tf32(float c[4], uint4 a, uint32_t b0, uint32_t b1) {
    asm volatile(
        "mma.sync.aligned.m16n8k8.row.col.f32.tf32.tf32.f32 "
        "{%0,%1,%2,%3}, {%4,%5,%6,%7}, {%8,%9}, {%0,%1,%2,%3};"
        : "+f"(c[0]), "+f"(c[1]), "+f"(c[2]), "+f"(c[3])
        : "r"(a.x), "r"(a.y), "r"(a.z), "r"(a.w), "r"(b0), "r"(b1));
}

__global__ __launch_bounds__(128, 2) void kv_gemm(
    const float* __restrict__ bk, const float* __restrict__ bv)
{
    extern __shared__ uint32_t sm[];

    const int tid  = threadIdx.x;
    const int warp = tid >> 5, lane = tid & 31;
    const int wm   = warp >> 1;
    const int wn   = warp & 1;
    const int lr   = lane >> 2;
    const int lc   = lane & 3;
    const int n0   = blockIdx.x * BN;
    const int m0   = blockIdx.y * BM;
    const int rt0  = m0 >> 4;
    const int nt0  = n0 >> 3;

    const uint32_t* pA = g_Xt + (size_t)rt0*65536u + tid*4;
    const uint32_t* pB = g_Wt + (size_t)(nt0 + (tid >> 6))*32768u + (tid & 63)*4;

    float acc[4][8][4];
    #pragma unroll
    for (int mi=0;mi<4;mi++)
        #pragma unroll
        for (int ni=0;ni<8;ni++)
            #pragma unroll
            for (int r=0;r<4;r++) acc[mi][ni][r] = 0.f;

    #define LOAD_STAGE(kt, SLOT)                                                     \
        do {                                                                         \
            uint32_t* da = sm + (SLOT)*STG_U + tid*4;                                \
            uint32_t* db = sm + (SLOT)*STG_U + 4096 + tid*4;                         \
            _Pragma("unroll")                                                        \
            for (int i = 0; i < 8; i++) {                                            \
                __pipeline_memcpy_async(da + i*512, pA + (size_t)i*65536u + (kt)*512, 16); \
                __pipeline_memcpy_async(db + i*512, pB + (size_t)i*65536u + (kt)*256, 16); \
            }                                                                        \
            __pipeline_commit();                                                     \
        } while (0)

    #define COMPUTE_STAGE(SLOT)                                                      \
        do {                                                                         \
            const uint32_t* Av = sm + (SLOT)*STG_U + wm*2048 + lane*4;               \
            const uint32_t* Bv = sm + (SLOT)*STG_U + 4096 + wn*2048 + lane*4;        \
            _Pragma("unroll")                                                        \
            for (int kp = 0; kp < 2; kp++) {                                         \
                uint4 bb[8];                                                         \
                _Pragma("unroll")                                                    \
                for (int ni = 0; ni < 8; ni++)                                       \
                    bb[ni] = *(const uint4*)(Bv + (ni*2 + kp)*128);                  \
                _Pragma("unroll")                                                    \
                for (int h = 0; h < 2; h++) {                                        \
                    const int ks = kp*2 + h;                                         \
                    uint4 aa[4];                                                     \
                    _Pragma("unroll")                                                \
                    for (int mi = 0; mi < 4; mi++)                                   \
                        aa[mi] = *(const uint4*)(Av + (mi*4 + ks)*128);              \
                    _Pragma("unroll")                                                \
                    for (int mi = 0; mi < 4; mi++)                                   \
                        _Pragma("unroll")                                            \
                        for (int ni = 0; ni < 8; ni++)                               \
                            mma_tf32(acc[mi][ni], aa[mi],                            \
                                     h ? bb[ni].z : bb[ni].x,                        \
                                     h ? bb[ni].w : bb[ni].y);                       \
                }                                                                    \
            }                                                                        \
        } while (0)

    #define GEMM_STEP(kt, SLOT, LOADSLOT)                                            \
        do {                                                                         \
            __pipeline_wait_prior(1);                                                \
            __syncthreads();                                                         \
            LOAD_STAGE((kt)+2, LOADSLOT);                                            \
            COMPUTE_STAGE(SLOT);                                                     \
        } while (0)

    LOAD_STAGE(0, 0);
    LOAD_STAGE(1, 1);

    for (int g = 0; g < 42; g++) {
        const int kt = g*3;
        GEMM_STEP(kt,   0, 2);
        GEMM_STEP(kt+1, 1, 0);
        GEMM_STEP(kt+2, 2, 1);
    }
    __pipeline_wait_prior(1);
    __syncthreads();
    COMPUTE_STAGE(0);
    __pipeline_wait_prior(0);
    __syncthreads();
    COMPUTE_STAGE(1);

    #undef GEMM_STEP
    #undef COMPUTE_STAGE
    #undef LOAD_STAGE

    const bool   isK  = (n0 < DV_);
    const float* bias = isK ? bk : bv;
    float*       gout = isK ? g_K : g_V;
    const int    nc0  = isK ? n0 : (n0 - DV_);

    #pragma unroll
    for (int mi = 0; mi < 4; mi++) {
        const int m = m0 + wm*64 + mi*16 + lr;
        #pragma unroll
        for (int ni = 0; ni < 8; ni++) {
            const int nc = nc0 + wn*64 + ni*8 + 2*lc;
            const float b0v = bias[nc], b1v = bias[nc+1];
            float2 v0 = { acc[mi][ni][0] + b0v, acc[mi][ni][1] + b1v };
            float2 v1 = { acc[mi][ni][2] + b0v, acc[mi][ni][3] + b1v };
            *(float2*)(gout + (size_t)m*DV_ + nc)     = v0;
            *(float2*)(gout + (size_t)(m+8)*DV_ + nc) = v1;
        }
    }
}

// ---------------- Qp = S @ Wq^T + bq (batch-invariant) -----------------------
__global__ __launch_bounds__(256) void qp_kernel(
    const float* __restrict__ S, const float* __restrict__ Wq, const float* __restrict__ bq)
{
    int gw   = (blockIdx.x*256 + threadIdx.x) >> 5;
    int lane = threadIdx.x & 31;
    int q = gw >> 10, j = gw & 1023;
    const float4* s4 = (const float4*)(S + q*DV_);
    const float4* w4 = (const float4*)(Wq + (size_t)j*DV_);
    float acc = 0.f;
    #pragma unroll
    for (int k = lane; k < 256; k += 32) {
        float4 a = s4[k], b = w4[k];
        acc += a.x*b.x + a.y*b.y + a.z*b.z + a.w*b.w;
    }
    acc = warp_red_sum(acc);
    if (lane == 0) g_Qp[q*DV_ + j] = acc + bq[j];
}

// ----- fused flash attention: 512 threads, 1 chunk/block, 2 half-slots -------
// half = tid>>8 handles keys [half*32, half*32+32) as independent z-slot 2z+half.
__global__ __launch_bounds__(512) void flash_kernel(const int* __restrict__ mask)
{
    __shared__ float qs[NS_*68];
    __shared__ float ks[64*68];
    __shared__ float vs[64*68];
    __shared__ float ps[64*40];
    __shared__ int   mks[64];
    const int h = blockIdx.x, b = blockIdx.y, z = blockIdx.z;   // z = chunk (0..31)
    const int tid  = threadIdx.x;
    const int half = tid >> 8;
    const int tq   = (tid >> 3) & 31;
    const int dg   = tid & 7;
    const float scale = 1.0f/32.0f;

    // staging: q 512 f4 (1/thread), K/V 1024 f4 each (2/thread each)
    {
        int qq = tid >> 4, d4 = tid & 15;
        if (tid < 512)
            __pipeline_memcpy_async(qs + qq*68 + d4*4, g_Qp + qq*DV_ + h*DH_ + d4*4, 16);
    }
    #pragma unroll
    for (int it = 0; it < 2; it++) {
        int idx = tid + it*512;
        int kk = idx >> 4, d4 = idx & 15;
        size_t row = (size_t)(b*L_ + z*64 + kk)*DV_ + h*DH_;
        __pipeline_memcpy_async(ks + kk*68 + d4*4, g_K + row + d4*4, 16);
        __pipeline_memcpy_async(vs + kk*68 + d4*4, g_V + row + d4*4, 16);
    }
    __pipeline_commit();
    if (tid < 64) mks[tid] = mask[b*L_ + z*64 + tid];
    __pipeline_wait_prior(0);
    __syncthreads();

    // scores: thread covers keys k = half*32 + dg + 8i, i<4
    float sc[4];
    #pragma unroll
    for (int i = 0; i < 4; i++) sc[i] = 0.f;
    const float4* q4 = (const float4*)(qs + tq*68);
    #pragma unroll
    for (int d = 0; d < 16; d++) {
        float4 a = q4[d];
        #pragma unroll
        for (int i = 0; i < 4; i++) {
            float4 c = ((const float4*)(ks + (half*32 + dg + i*8)*68))[d];
            sc[i] += a.x*c.x + a.y*c.y + a.z*c.z + a.w*c.w;
        }
    }
    #pragma unroll
    for (int i = 0; i < 4; i++)
        sc[i] = mks[half*32 + dg + i*8] ? sc[i]*scale : -1.0e30f;

    // per (tq, half) softmax over 32 keys: shuffle over dg (lanes xor 1,2,4)
    float cm = sc[0];
    #pragma unroll
    for (int i = 1; i < 4; i++) cm = fmaxf(cm, sc[i]);
    #pragma unroll
    for (int o = 1; o < 8; o <<= 1) cm = fmaxf(cm, __shfl_xor_sync(0xffffffffu, cm, o));

    float psum = 0.f;
    #pragma unroll
    for (int i = 0; i < 4; i++) {
        sc[i] = __expf(sc[i] - cm);
        psum += sc[i];
    }
    #pragma unroll
    for (int o = 1; o < 8; o <<= 1) psum += __shfl_xor_sync(0xffffffffu, psum, o);

    #pragma unroll
    for (int i = 0; i < 4; i++) ps[(half*32 + tq)*40 + dg + i*8] = sc[i];
    __syncthreads();

    // A.V over this half's 32 keys
    float4 o0 = {0,0,0,0}, o1 = {0,0,0,0};
    const float4* ps4 = (const float4*)(ps + (half*32 + tq)*40);
    #pragma unroll 4
    for (int t = 0; t < 8; t++) {
        float4 p = ps4[t];
        const int kb = half*32 + t*4;
        const float4* v0p = (const float4*)(vs + (kb+0)*68 + dg*8);
        const float4* v1p = (const float4*)(vs + (kb+1)*68 + dg*8);
        const float4* v2p = (const float4*)(vs + (kb+2)*68 + dg*8);
        const float4* v3p = (const float4*)(vs + (kb+3)*68 + dg*8);
        float4 a, c;
        a = v0p[0]; c = v0p[1];
        o0.x += p.x*a.x; o0.y += p.x*a.y; o0.z += p.x*a.z; o0.w += p.x*a.w;
        o1.x += p.x*c.x; o1.y += p.x*c.y; o1.z += p.x*c.z; o1.w += p.x*c.w;
        a = v1p[0]; c = v1p[1];
        o0.x += p.y*a.x; o0.y += p.y*a.y; o0.z += p.y*a.z; o0.w += p.y*a.w;
        o1.x += p.y*c.x; o1.y += p.y*c.y; o1.z += p.y*c.z; o1.w += p.y*c.w;
        a = v2p[0]; c = v2p[1];
        o0.x += p.z*a.x; o0.y += p.z*a.y; o0.z += p.z*a.z; o0.w += p.z*a.w;
        o1.x += p.z*c.x; o1.y += p.z*c.y; o1.z += p.z*c.z; o1.w += p.z*c.w;
        a = v3p[0]; c = v3p[1];
        o0.x += p.w*a.x; o0.y += p.w*a.y; o0.z += p.w*a.z; o0.w += p.w*a.w;
        o1.x += p.w*c.x; o1.y += p.w*c.y; o1.z += p.w*c.z; o1.w += p.w*c.w;
    }

    const int z2 = z*2 + half;
    float4* o4 = (float4*)(g_AOp + (size_t)z2*(B_*NS_*DV_) + (size_t)(b*NS_+tq)*DV_ + h*DH_ + dg*8);
    o4[0] = o0; o4[1] = o1;
    if (dg == 0) {
        int idx = ((z2*B_ + b)*H_ + h)*NS_ + tq;
        g_M[idx] = cm;
        g_S[idx] = psum;
    }
}

// -------- epilogue A0: merge 64 partial slots + residual + LN0 -> g_X ---------
__global__ __launch_bounds__(256) void epi_ln0(
    const float* __restrict__ S,
    const float* __restrict__ g0, const float* __restrict__ be0)
{
    __shared__ float coef[H_][AVS];
    __shared__ float redA[8], redB[8];
    const int row = blockIdx.x;           // 0..255
    const int b   = row >> 5;
    const int q   = row & 31;
    const int tid = threadIdx.x, w = tid >> 5, lane = tid & 31;

    if (tid < H_) {
        const int hh = tid;
        // pass 1: max
        float M = -3.0e38f;
        for (int z = 0; z < AVS; z++)
            M = fmaxf(M, g_M[((z*B_ + b)*H_ + hh)*NS_ + q]);
        // pass 2: weights + denominator
        float den = 0.f;
        for (int z = 0; z < AVS; z++) {
            int idx = ((z*B_ + b)*H_ + hh)*NS_ + q;
            float wz = __expf(g_M[idx] - M);
            coef[hh][z] = wz;
            den += wz * g_S[idx];
        }
        float inv = 1.0f/den;
        for (int z = 0; z < AVS; z++) coef[hh][z] *= inv;
    }
    __syncthreads();

    const int k  = tid;                   // float4 index 0..255
    const int hh = k >> 4;
    float4 v = ((const float4*)(S + (size_t)q*DV_))[k];
    for (int z = 0; z < AVS; z++) {
        float c = coef[hh][z];
        float4 a = ((const float4*)(g_AOp + (size_t)z*(B_*NS_*DV_) + (size_t)row*DV_))[k];
        v.x += c*a.x; v.y += c*a.y; v.z += c*a.z; v.w += c*a.w;
    }
    float s  = v.x+v.y+v.z+v.w;
    float sq = v.x*v.x+v.y*v.y+v.z*v.z+v.w*v.w;
    s = warp_red_sum(s); sq = warp_red_sum(sq);
    if (lane==0){ redA[w]=s; redB[w]=sq; }
    __syncthreads();
    float sum=0.f, ssq=0.f;
    #pragma unroll
    for (int i=0;i<8;i++){ sum+=redA[i]; ssq+=redB[i]; }
    float mu = sum*(1.0f/DV_);
    float rs = rsqrtf(ssq*(1.0f/DV_) - mu*mu + 1e-5f);
    float4 g = ((const float4*)g0)[k], be = ((const float4*)be0)[k];
    float4 r;
    r.x = (v.x-mu)*rs*g.x + be.x;
    r.y = (v.y-mu)*rs*g.y + be.y;
    r.z = (v.z-mu)*rs*g.z + be.z;
    r.w = (v.w-mu)*rs*g.w + be.w;
    ((float4*)(g_X + (size_t)row*DV_))[k] = r;
}

// -------- epilogue A1: o2 = x + relu(x @ Wo^T + bo) -> g_O2 -------------------
__global__ __launch_bounds__(256) void epi_gemm(
    const float* __restrict__ Wo, const float* __restrict__ bo)
{
    __shared__ __align__(16) float xbuf[8][1024];
    const int tid = threadIdx.x, w = tid >> 5, lane = tid & 31;
    const int cg = blockIdx.x;            // 0..7, 128 cols each
    const int row0 = blockIdx.y * 8;

    {
        const int row = row0 + w;
        const float4* Xr = (const float4*)(g_X + (size_t)row*DV_);
        #pragma unroll
        for (int i = 0; i < 8; i++) {
            int k = lane + i*32;
            ((float4*)xbuf[w])[k] = Xr[k];
        }
    }
    __syncthreads();

    for (int t = 0; t < 2; t++) {
        const int jbase = cg*128 + w*16 + t*8;
        const float4* wrow[8];
        #pragma unroll
        for (int jj = 0; jj < 8; jj++)
            wrow[jj] = (const float4*)(Wo + (size_t)(jbase+jj)*DV_);
        float acc[8][8];
        #pragma unroll
        for (int jj=0;jj<8;jj++)
            #pragma unroll
            for (int r=0;r<8;r++) acc[jj][r] = 0.f;

        for (int k = lane; k < 256; k += 32) {
            float4 xv[8];
            #pragma unroll
            for (int r = 0; r < 8; r++) xv[r] = ((const float4*)xbuf[r])[k];
            #pragma unroll
            for (int jj = 0; jj < 8; jj++) {
                float4 wv = wrow[jj][k];
                #pragma unroll
                for (int r = 0; r < 8; r++)
                    acc[jj][r] += wv.x*xv[r].x + wv.y*xv[r].y + wv.z*xv[r].z + wv.w*xv[r].w;
            }
        }
        #pragma unroll
        for (int jj = 0; jj < 8; jj++) {
            const int j = jbase + jj;
            const float bov = bo[j];
            #pragma unroll
            for (int r = 0; r < 8; r++) {
                float tot = warp_red_sum(acc[jj][r]);
                if (lane == r)
                    g_O2[(size_t)(row0+r)*DV_ + j] = xbuf[r][j] + fmaxf(tot + bov, 0.f);
            }
        }
    }
}

// -------- epilogue B: LN1 -> out -------------------------------------------------
__global__ __launch_bounds__(256) void epi_ln1(
    const float* __restrict__ g1, const float* __restrict__ be1, float* __restrict__ out)
{
    __shared__ float redA[8], redB[8];
    const int row = blockIdx.x;
    const int tid = threadIdx.x, w = tid>>5, lane = tid&31;
    const float4* o4 = (const float4*)(g_O2 + (size_t)row*DV_);
    float4 v = o4[tid];
    float s  = v.x+v.y+v.z+v.w;
    float sq = v.x*v.x+v.y*v.y+v.z*v.z+v.w*v.w;
    s = warp_red_sum(s); sq = warp_red_sum(sq);
    if (lane==0){ redA[w]=s; redB[w]=sq; }
    __syncthreads();
    float sum=0.f, ssq=0.f;
    #pragma unroll
    for (int i=0;i<8;i++){ sum+=redA[i]; ssq+=redB[i]; }
    float mu = sum*(1.0f/DV_);
    float rs = rsqrtf(ssq*(1.0f/DV_) - mu*mu + 1e-5f);
    float4 g = ((const float4*)g1)[tid], be = ((const float4*)be1)[tid];
    float4 r;
    r.x = (v.x-mu)*rs*g.x + be.x;
    r.y = (v.y-mu)*rs*g.y + be.y;
    r.z = (v.z-mu)*rs*g.z + be.z;
    r.w = (v.w-mu)*rs*g.w + be.w;
    ((float4*)(out + (size_t)row*DV_))[tid] = r;
}

// =============================== launch =======================================
extern "C" void kernel_launch(void* const* d_in, const int* in_sizes, int n_in,
                              void* d_out, int out_size)
{
    const float* X    = (const float*)d_in[0];
    const int*   mask = (const int*)  d_in[1];
    const float* S    = (const float*)d_in[2];
    const float* Wq   = (const float*)d_in[3];
    const float* bq   = (const float*)d_in[4];
    const float* Wk   = (const float*)d_in[5];
    const float* bk   = (const float*)d_in[6];
    const float* Wv   = (const float*)d_in[7];
    const float* bv   = (const float*)d_in[8];
    const float* Wo   = (const float*)d_in[9];
    const float* bo   = (const float*)d_in[10];
    const float* g0   = (const float*)d_in[11];
    const float* be0  = (const float*)d_in[12];
    const float* g1   = (const float*)d_in[13];
    const float* be1  = (const float*)d_in[14];
    float* out = (float*)d_out;

    const int SMEM_DYN = NSTG * STG_U * (int)sizeof(uint32_t);   // 98304
    cudaFuncSetAttribute(kv_gemm, cudaFuncAttributeMaxDynamicSharedMemorySize, SMEM_DYN);

    cvt_kernel  <<<XT_BLOCKS + WT_BLOCKS, 256>>>(X, Wk, Wv);            // launch 1
    qp_kernel   <<<4096, 256>>>(S, Wq, bq);                             // launch 2
    kv_gemm     <<<dim3(N2_/BN, M_/BM), 128, SMEM_DYN>>>(bk, bv);       // launch 3
    flash_kernel<<<dim3(H_, B_, AVS/2), 512>>>(mask);                   // launch 4 (profiled)
    epi_ln0     <<<B_*NS_, 256>>>(S, g0, be0);                          // launch 5
    epi_gemm    <<<dim3(8, 32), 256>>>(Wo, bo);                         // launch 6
    epi_ln1     <<<B_*NS_, 256>>>(g1, be1, out);                        // launch 7
}